// round 17
// baseline (speedup 1.0000x reference)
#include <cuda_runtime.h>
#include <cuda_fp16.h>
#include <cuda_pipeline.h>

#define T    512
#define K    4
#define G    20000
#define EPG  3
#define B    512

#define BT     32                  // batches per tile (= lanes)
#define NBT    (B / BT)            // 16
#define BLKG   1024                // 32 warps = 4 groups of 8
#define GPB    256                 // g per super-chunk (64 per group)
#define GPG    64                  // g per group-chunk
#define GTHR   256                 // threads per group
#define CPS    9                   // chunks per split
#define NSPLIT 9                   // grid 16*9 = 144 = 1 wave (1 block/SM)
#define TSLICE 57                  // t per split for h2 compute (9*57 >= 512)

// h2 fp16, layout [bt][t][b_in] as uint2 (k0k1, k2k3): 2 MB, L2-resident.
__device__ uint2 g_h2u[NBT * T * BT];
// per-(bt, slice) ready flags + per-bt departure counters (zero-init; the
// kernel resets them at exit so graph replays start clean).
__device__ int g_flag[NBT * NSPLIT];
__device__ int g_depart[NBT];

// SMEM (bytes): h2 128K | rec 4 groups x 2 bufs x 4K | out 4 x 2 x 8K = 224K
#define S_H2   0
#define S_REC  131072                    // + gid*8192 + buf*4096
#define S_OUT  (131072 + 32768)          // + gid*16384 + buf*8192
#define SMEM_TOTAL (131072 + 32768 + 65536)

__device__ __forceinline__ float leaky(float x) {
    return x > 0.0f ? x : 0.01f * x;
}

// Packed f32x2 FMA (Blackwell FFMA2) — bit-identical to two scalar fp32 FMAs.
__device__ __forceinline__ float2 ffma2(float2 a, float2 b, float2 c) {
    float2 d;
    asm("{\n\t"
        ".reg .b64 ra, rb, rc, rd;\n\t"
        "mov.b64 ra, {%2, %3};\n\t"
        "mov.b64 rb, {%4, %5};\n\t"
        "mov.b64 rc, {%6, %7};\n\t"
        "fma.rn.f32x2 rd, ra, rb, rc;\n\t"
        "mov.b64 {%0, %1}, rd;\n\t"
        "}"
        : "=f"(d.x), "=f"(d.y)
        : "f"(a.x), "f"(a.y), "f"(b.x), "f"(b.y), "f"(c.x), "f"(c.y));
    return d;
}

// Stage one GROUP chunk (64 g) from RAW inputs with 256 threads:
//   tg in [0,64):    pack q0 = {e0*16, e1*16, e2*16, b3} via LDG -> STS
//   tg in [64,256):  w3 quarters via cp.async (192 float4)
__device__ __forceinline__ void stage_rec(float4* rec,
                                          const int*   __restrict__ edge,
                                          const float* __restrict__ b3,
                                          const float* __restrict__ w3,
                                          int go, int tg) {
    if (tg < GPG) {
        const int g = go + tg;
        float4 q;
        if (g < G) {
            q = make_float4(__int_as_float(edge[3 * g + 0] * 16),
                            __int_as_float(edge[3 * g + 1] * 16),
                            __int_as_float(edge[3 * g + 2] * 16),
                            b3[g]);
        } else {
            q = make_float4(__int_as_float(0), __int_as_float(0),
                            __int_as_float(0), 0.f);
        }
        rec[tg * 4] = q;
    } else {
        const int i = tg - GPG;                     // 0..191
        const int nvg = min(GPG, max(0, G - go));
        if (i < nvg * 3) {
            const float4* wsrc =
                reinterpret_cast<const float4*>(w3 + (size_t)go * 12);
            const int g = i / 3, part = i - g * 3;
            __pipeline_memcpy_async(&rec[g * 4 + 1 + part], &wsrc[i], 16);
        }
    }
}

// ---------------------------------------------------------------------------
// Single fused kernel. Phase A: 9 blocks per bt each compute a 57-t slice of
// that bt's h2 into global, setting a per-slice flag. Tile staging is
// per-warp: each staging warp spins only on the (<=2) slices it covers, so
// staging overlaps sibling-block skew. Phase B: 4-group gather pipeline.
// ---------------------------------------------------------------------------
__global__ void __launch_bounds__(BLKG, 1)
fused_kernel(const float*  __restrict__ features,
             const float4* __restrict__ w1,
             const float4* __restrict__ b1,
             const float4* __restrict__ w2,
             const float4* __restrict__ b2,
             const float*  __restrict__ w3,
             const float*  __restrict__ b3,
             const int*    __restrict__ edge,
             float*        __restrict__ out) {
    extern __shared__ char sm[];
    const uint4* s_h2q = reinterpret_cast<const uint4*>(sm + S_H2);  // [T*16]

    const int tid   = threadIdx.x;
    const int split = blockIdx.x;   // 0..8
    const int bt    = blockIdx.y;   // 0..15
    const int w     = tid >> 5;
    const int lane  = tid & 31;
    const int gid   = w >> 3;             // pipeline group 0..3
    const int wg    = w & 7;              // warp within group
    const int tg    = tid & (GTHR - 1);   // thread within group
    const int half  = lane >> 4;
    const int hb    = lane & 15;

    float4* g_rec = reinterpret_cast<float4*>(sm + S_REC + gid * 8192);
    float*  g_out = reinterpret_cast<float*>(sm + S_OUT + gid * 16384);

    // ---- Phase A1: compute this block's h2 slice (t in [split*57, +57)) ----
    {
        const int t0   = split * TSLICE;
        const int tcnt = min(TSLICE, T - t0);        // 57 (56 for split 8)
        const int n    = tcnt * BT;
        for (int i = tid; i < n; i += BLKG) {
            const int t    = t0 + (i >> 5);
            const int b_in = i & 31;
            const int b    = bt * BT + b_in;

            const float  f   = features[b * T + t];
            const float4 w1v = w1[t];
            const float4 b1v = b1[t];
            const float4 b2v = b2[t];

            const float h0 = leaky(fmaf(f, w1v.x, b1v.x));
            const float h1 = leaky(fmaf(f, w1v.y, b1v.y));
            const float h2 = leaky(fmaf(f, w1v.z, b1v.z));
            const float h3 = leaky(fmaf(f, w1v.w, b1v.w));

            const float4 w20 = w2[t * 4 + 0];
            const float4 w21 = w2[t * 4 + 1];
            const float4 w22 = w2[t * 4 + 2];
            const float4 w23 = w2[t * 4 + 3];

            float4 o;
            o.x = leaky(fmaf(h3, w23.x, fmaf(h2, w22.x, fmaf(h1, w21.x, fmaf(h0, w20.x, b2v.x)))));
            o.y = leaky(fmaf(h3, w23.y, fmaf(h2, w22.y, fmaf(h1, w21.y, fmaf(h0, w20.y, b2v.y)))));
            o.z = leaky(fmaf(h3, w23.z, fmaf(h2, w22.z, fmaf(h1, w21.z, fmaf(h0, w20.z, b2v.z)))));
            o.w = leaky(fmaf(h3, w23.w, fmaf(h2, w22.w, fmaf(h1, w21.w, fmaf(h0, w20.w, b2v.w)))));

            const __half2 p0 = __floats2half2_rn(o.x, o.y);
            const __half2 p1 = __floats2half2_rn(o.z, o.w);
            uint2 p;
            p.x = *reinterpret_cast<const unsigned int*>(&p0);
            p.y = *reinterpret_cast<const unsigned int*>(&p1);
            g_h2u[((size_t)bt * T + t) * BT + b_in] = p;
        }
    }
    __threadfence();          // publish this thread's h2 writes (GPU scope)
    __syncthreads();          // all fences in this block done
    if (tid == 0) atomicExch(&g_flag[bt * NSPLIT + split], 1);

    // ---- Phase A2: stage chunk-0 records (raw, prep-independent) ----
    int c = split;   // first super-chunk for this split
    stage_rec(g_rec, edge, b3, w3, c * GPB + gid * GPG, tg);
    __pipeline_commit();

    // ---- Phase A3: per-warp pipelined tile staging. Warp w covers uint4
    // indices [w*256, (w+1)*256) = t in [w*16, w*16+16), intersecting <= 2
    // slices; it waits only for those, overlapping stage with sibling skew.
    {
        const int t_lo = w * 16;
        const int s_lo = t_lo / TSLICE;
        const int s_hi = (t_lo + 15) / TSLICE;
        if (lane == 0) {
            while (*((volatile int*)&g_flag[bt * NSPLIT + s_lo]) == 0) { }
            if (s_hi != s_lo)
                while (*((volatile int*)&g_flag[bt * NSPLIT + s_hi]) == 0) { }
            __threadfence();   // acquire: order the stage reads below
        }
        __syncwarp();

        const uint4* src = reinterpret_cast<const uint4*>(g_h2u + (size_t)bt * T * BT);
        uint4*       dst = reinterpret_cast<uint4*>(sm + S_H2);
        #pragma unroll
        for (int j = 0; j < 8; j++) {
            const int i = w * 256 + j * 32 + lane;
            __pipeline_memcpy_async(&dst[i], &src[i], 16);
        }
    }
    __pipeline_commit();
    __pipeline_wait_prior(0);
    __syncthreads();          // full h2 tile + chunk-0 rec published

    const int barid = 1 + gid;

    // ---- Phase B: 4-group gather pipeline ----
    #pragma unroll 1
    for (int iter = 0; iter < CPS; iter++) {
        const int  buf      = iter & 1;
        const bool has_next = (iter + 1 < CPS);
        const int  go       = c * GPB + gid * GPG;

        if (has_next) {
            stage_rec(g_rec + (buf ^ 1) * (GPG * 4), edge, b3, w3,
                      (c + NSPLIT) * GPB + gid * GPG, tg);
            __pipeline_commit();
        }

        if (go < G) {   // skip fully-padded group-chunks
            const float4* rec = g_rec + buf * (GPG * 4);
            float*        ob  = g_out + buf * (GPG * 32);
            const int gl0 = wg * 8;

            #pragma unroll
            for (int pp = 0; pp < 4; pp++) {
                const int gsel = gl0 + 2 * pp + half;
                const int xs   = gsel & 31;

                const float4 q0 = rec[gsel * 4 + 0];
                const float4 q1 = rec[gsel * 4 + 1];
                const float4 q2 = rec[gsel * 4 + 2];
                const float4 q3 = rec[gsel * 4 + 3];

                const uint4 h0 = s_h2q[__float_as_int(q0.x) + hb];
                const uint4 h1 = s_h2q[__float_as_int(q0.y) + hb];
                const uint4 h2 = s_h2q[__float_as_int(q0.z) + hb];

                float2 a00 = make_float2(q0.w, 0.f), a01 = make_float2(0.f, 0.f);
                float2 a10 = make_float2(q0.w, 0.f), a11 = make_float2(0.f, 0.f);

                a00 = ffma2(__half22float2(*reinterpret_cast<const __half2*>(&h0.x)),
                            make_float2(q1.x, q1.y), a00);
                a01 = ffma2(__half22float2(*reinterpret_cast<const __half2*>(&h0.y)),
                            make_float2(q1.z, q1.w), a01);
                a10 = ffma2(__half22float2(*reinterpret_cast<const __half2*>(&h0.z)),
                            make_float2(q1.x, q1.y), a10);
                a11 = ffma2(__half22float2(*reinterpret_cast<const __half2*>(&h0.w)),
                            make_float2(q1.z, q1.w), a11);

                a00 = ffma2(__half22float2(*reinterpret_cast<const __half2*>(&h1.x)),
                            make_float2(q2.x, q2.y), a00);
                a01 = ffma2(__half22float2(*reinterpret_cast<const __half2*>(&h1.y)),
                            make_float2(q2.z, q2.w), a01);
                a10 = ffma2(__half22float2(*reinterpret_cast<const __half2*>(&h1.z)),
                            make_float2(q2.x, q2.y), a10);
                a11 = ffma2(__half22float2(*reinterpret_cast<const __half2*>(&h1.w)),
                            make_float2(q2.z, q2.w), a11);

                a00 = ffma2(__half22float2(*reinterpret_cast<const __half2*>(&h2.x)),
                            make_float2(q3.x, q3.y), a00);
                a01 = ffma2(__half22float2(*reinterpret_cast<const __half2*>(&h2.y)),
                            make_float2(q3.z, q3.w), a01);
                a10 = ffma2(__half22float2(*reinterpret_cast<const __half2*>(&h2.z)),
                            make_float2(q3.x, q3.y), a10);
                a11 = ffma2(__half22float2(*reinterpret_cast<const __half2*>(&h2.w)),
                            make_float2(q3.z, q3.w), a11);

                const float r0 = (a00.x + a01.x) + (a00.y + a01.y);
                const float r1 = (a10.x + a11.x) + (a10.y + a11.y);

                ob[gsel * 32 + ((2 * hb)     ^ xs)] = r0;
                ob[gsel * 32 + ((2 * hb + 1) ^ xs)] = r1;
            }
        }

        if (has_next) __pipeline_wait_prior(0);
        asm volatile("bar.sync %0, %1;" :: "r"(barid), "r"(GTHR) : "memory");

        // Coalesced write-out: warp wg covers batch rows wg+{0,8,16,24}.
        if (go < G) {
            const float* ob = g_out + buf * (GPG * 32);
            if (go + GPG <= G) {   // fast path: whole chunk valid
                #pragma unroll
                for (int bh = 0; bh < 4; bh++) {
                    const int b_local = wg + bh * 8;
                    float* orow = out + (size_t)(bt * BT + b_local) * G + go;
                    #pragma unroll
                    for (int it2 = 0; it2 < 2; it2++) {
                        const int gl = it2 * 32 + lane;
                        orow[gl] = ob[gl * 32 + (b_local ^ (gl & 31))];
                    }
                }
            } else {               // tail chunk: per-element guard
                #pragma unroll
                for (int bh = 0; bh < 4; bh++) {
                    const int b_local = wg + bh * 8;
                    float* orow = out + (size_t)(bt * BT + b_local) * G + go;
                    #pragma unroll
                    for (int it2 = 0; it2 < 2; it2++) {
                        const int gl = it2 * 32 + lane;
                        if (go + gl < G)
                            orow[gl] = ob[gl * 32 + (b_local ^ (gl & 31))];
                    }
                }
            }
        }

        c += NSPLIT;
    }

    // ---- Epilogue: counter/flag reset so graph replays start from zero ----
    if (tid == 0) {
        atomicAdd(&g_depart[bt], 1);
        if (split == 0) {
            while (*((volatile int*)&g_depart[bt]) < NSPLIT) { }
            #pragma unroll
            for (int j = 0; j < NSPLIT; j++)
                atomicExch(&g_flag[bt * NSPLIT + j], 0);
            atomicExch(&g_depart[bt], 0);
        }
    }
}

extern "C" void kernel_launch(void* const* d_in, const int* in_sizes, int n_in,
                              void* d_out, int out_size) {
    const float* features = (const float*)d_in[0];   // [B, T]
    const float* w1       = (const float*)d_in[1];   // [T, K]
    const float* b1       = (const float*)d_in[2];   // [T, K]
    const float* w2       = (const float*)d_in[3];   // [T, K, K]
    const float* b2       = (const float*)d_in[4];   // [T, K]
    const float* w3       = (const float*)d_in[5];   // [G, EPG, K]
    const float* b3       = (const float*)d_in[6];   // [G]
    const int*   edge     = (const int*)  d_in[7];   // [G, EPG]
    float*       out      = (float*)d_out;           // [B, G]

    cudaFuncSetAttribute(fused_kernel,
                         cudaFuncAttributeMaxDynamicSharedMemorySize, SMEM_TOTAL);
    dim3 grid(NSPLIT, NBT);
    fused_kernel<<<grid, BLKG, SMEM_TOTAL>>>(
        features, (const float4*)w1, (const float4*)b1,
        (const float4*)w2, (const float4*)b2,
        w3, b3, edge, out);
}